// round 12
// baseline (speedup 1.0000x reference)
#include <cuda_runtime.h>

// ConvKB: score[e] = sum_{c,d} relu(w0c*u_d + w1c*v_d + w2c*r_d + bc) * lw[c,d] + lb
// Warp = (edge, 8 channels, all 128 d); 4 warps/block share an edge (L1-hit gathers).
// 3-stage pipeline (idx staged 2 iters ahead, gathers 1 ahead) + unroll-2.
// NO warp reduction: every lane fire-and-forget red.global.add.f32 into out[e]
// (zero-stall; L2 atomic ALU does the sum off the critical path).
// Packed f32x2 FMA, relu via (t+|t|) with lw pre-scaled 0.5, out pre-init to lin_b.

#define D 128
#define THREADS 128
#define BLOCKS 444            // 148 SMs * 3 blocks
#define NEDGE 50000

typedef unsigned long long ull;

__device__ int g_is64;        // 1 if index arrays are int64, 0 if int32

__device__ __forceinline__ ull ffma2(ull a, ull b, ull c) {
    ull d;
    asm("fma.rn.f32x2 %0, %1, %2, %3;" : "=l"(d) : "l"(a), "l"(b), "l"(c));
    return d;
}
__device__ __forceinline__ ull fadd2(ull a, ull b) {
    ull d;
    asm("add.rn.f32x2 %0, %1, %2;" : "=l"(d) : "l"(a), "l"(b));
    return d;
}
// 2*relu(a) packed: a + |a|
__device__ __forceinline__ ull relu2x2(ull a) {
    return fadd2(a, a & 0x7FFFFFFF7FFFFFFFULL);
}
__device__ __forceinline__ ull pack2(float lo, float hi) {
    ull d;
    asm("mov.b64 %0, {%1, %2};" : "=l"(d) : "f"(lo), "f"(hi));
    return d;
}
__device__ __forceinline__ float2 unpack2(ull v) {
    float2 r;
    asm("mov.b64 {%0, %1}, %2;" : "=f"(r.x), "=f"(r.y) : "l"(v));
    return r;
}
// Fire-and-forget global float add (RED: no return, no scoreboard wait).
__device__ __forceinline__ void red_add(float* p, float v) {
    asm volatile("red.global.add.f32 [%0], %1;" :: "l"(p), "f"(v) : "memory");
}

// Fused: dtype detection (thread 0) + out[] init to lin_b.
__global__ void init_kernel(float* __restrict__ out, const float* __restrict__ lin_b,
                            const int* __restrict__ ei) {
    int i = blockIdx.x * blockDim.x + threadIdx.x;
    if (i == 0) {
        int is64 = 1;
        for (int k = 1; k < 128; k += 2)
            if (ei[k] != 0) { is64 = 0; break; }
        g_is64 = is64;
    }
    if (i < NEDGE) out[i] = lin_b[0];
}

__global__ void __launch_bounds__(THREADS, 3) convkb_kernel(
    const float* __restrict__ h,
    const float* __restrict__ g,
    const int* __restrict__ edge_idx,    // [2,E], low int32 words read
    const int* __restrict__ edge_type,   // [E]
    const float* __restrict__ conv_w,    // [C,3]
    const float* __restrict__ conv_b,    // [C]
    const float* __restrict__ lin_w,     // [C*D]
    float* __restrict__ out)             // [E], pre-initialized to lin_b
{
    const int lane = threadIdx.x & 31;
    const int warp = threadIdx.x >> 5;

    // ---- Edge-invariant register state: warp covers channels cb..cb+7 ----
    // Lane L owns d = 4L .. 4L+3 (two packed d-pairs).
    const int cb = warp * 8;
    ull w0d[8], w1d[8], w2d[8], bd[8], lwr[8][2];
    {
        const float4* lw4 = (const float4*)lin_w;
#pragma unroll
        for (int ch = 0; ch < 8; ++ch) {
            int c = cb + ch;
            float a0 = conv_w[3 * c + 0], a1 = conv_w[3 * c + 1], a2 = conv_w[3 * c + 2];
            float bb = conv_b[c];
            w0d[ch] = pack2(a0, a0);
            w1d[ch] = pack2(a1, a1);
            w2d[ch] = pack2(a2, a2);
            bd[ch]  = pack2(bb, bb);
            float4 A = lw4[c * 32 + lane];   // lw[c, 4L .. 4L+3]
            lwr[ch][0] = pack2(0.5f * A.x, 0.5f * A.y);   // relu-trick pre-scale
            lwr[ch][1] = pack2(0.5f * A.z, 0.5f * A.w);
        }
    }

    const int stride = g_is64 ? 2 : 1;

    // ---- Pipeline prologue: data for e0, indices for e0+BLOCKS ----
    int e = (int)blockIdx.x;                       // < NEDGE always
    ulonglong2 U, V, R;
    {
        int row = edge_idx[(size_t)stride * e];
        int col = edge_idx[(size_t)stride * (NEDGE + e)];
        int rel = edge_type[(size_t)stride * e];
        U = ((const ulonglong2*)(h + (size_t)row * D))[lane];
        V = ((const ulonglong2*)(h + (size_t)col * D))[lane];
        R = ((const ulonglong2*)(g + (size_t)rel * D))[lane];
    }
    int e1 = min(e + BLOCKS, NEDGE - 1);           // clamp: safe addr, discarded
    int row1 = edge_idx[(size_t)stride * e1];
    int col1 = edge_idx[(size_t)stride * (NEDGE + e1)];
    int rel1 = edge_type[(size_t)stride * e1];

#pragma unroll 2
    for (; e < NEDGE; e += BLOCKS) {
        // Issue next edge's gathers (indices staged last iteration).
        ulonglong2 NU = ((const ulonglong2*)(h + (size_t)row1 * D))[lane];
        ulonglong2 NV = ((const ulonglong2*)(h + (size_t)col1 * D))[lane];
        ulonglong2 NR = ((const ulonglong2*)(g + (size_t)rel1 * D))[lane];

        // Stage indices for e + 2*BLOCKS.
        int e2 = min(e + 2 * BLOCKS, NEDGE - 1);
        int row2 = edge_idx[(size_t)stride * e2];
        int col2 = edge_idx[(size_t)stride * (NEDGE + e2)];
        int rel2 = edge_type[(size_t)stride * e2];

        // ---- Compute current edge (data pre-packed as ull pairs) ----
        ull acc0 = 0ULL, acc1 = 0ULL;
#pragma unroll
        for (int ch = 0; ch < 8; ++ch) {
            ull t0 = ffma2(w2d[ch], R.x, bd[ch]);
            ull t1 = ffma2(w2d[ch], R.y, bd[ch]);
            t0 = ffma2(w1d[ch], V.x, t0);
            t1 = ffma2(w1d[ch], V.y, t1);
            t0 = ffma2(w0d[ch], U.x, t0);
            t1 = ffma2(w0d[ch], U.y, t1);
            t0 = relu2x2(t0);
            t1 = relu2x2(t1);
            acc0 = ffma2(t0, lwr[ch][0], acc0);
            acc1 = ffma2(t1, lwr[ch][1], acc1);
        }
        float2 a = unpack2(fadd2(acc0, acc1));
        red_add(out + e, a.x + a.y);   // every lane; L2 atomic ALU sums, zero stall

        // ---- Rotate pipeline (renamed away by unroll-2) ----
        U = NU; V = NV; R = NR;
        row1 = row2; col1 = col2; rel1 = rel2;
    }
}

extern "C" void kernel_launch(void* const* d_in, const int* in_sizes, int n_in,
                              void* d_out, int out_size) {
    // Identify inputs by unique element counts (immune to metadata ordering).
    const float *h = 0, *g = 0, *conv_w = 0, *conv_b = 0, *lin_w = 0, *lin_b = 0;
    const int *edge_idx = 0, *edge_type = 0;
    for (int i = 0; i < n_in; ++i) {
        switch (in_sizes[i]) {
            case NEDGE * 128: h         = (const float*)d_in[i]; break;
            case 500 * 128:   g         = (const float*)d_in[i]; break;
            case 2 * NEDGE:   edge_idx  = (const int*)d_in[i];   break;
            case NEDGE:       edge_type = (const int*)d_in[i];   break;
            case 96:          conv_w    = (const float*)d_in[i]; break;
            case 32:          conv_b    = (const float*)d_in[i]; break;
            case 4096:        lin_w     = (const float*)d_in[i]; break;
            case 1:           lin_b     = (const float*)d_in[i]; break;
            default: break;
        }
    }
    float* out = (float*)d_out;

    init_kernel<<<(NEDGE + 255) / 256, 256>>>(out, lin_b, edge_idx);
    convkb_kernel<<<BLOCKS, THREADS>>>(h, g, edge_idx, edge_type,
                                       conv_w, conv_b, lin_w, out);
}

// round 13
// speedup vs baseline: 2.1107x; 2.1107x over previous
#include <cuda_runtime.h>

// ConvKB: score[e] = sum_{c,d} relu(w0c*u_d + w1c*v_d + w2c*r_d + bc) * lw[c,d] + lb
// Warp = (2 edges, 8 channels, all 128 d) — params shared across both edges.
// 3-stage pipeline (idx 2 iters ahead, gathers 1 ahead). Two interleaved shuffle
// butterflies + lane-0 atomicAdd (proven R10 path). Packed f32x2 FMA, relu via
// (t+|t|) with lw pre-scaled 0.5, out pre-initialized to lin_b.

#define D 128
#define THREADS 128
#define G 296                 // grid: 148 SMs * 2 blocks
#define STEP (2 * G)          // edges consumed per iteration across grid
#define NEDGE 50000

typedef unsigned long long ull;

__device__ int g_is64;        // 1 if index arrays are int64, 0 if int32

__device__ __forceinline__ ull ffma2(ull a, ull b, ull c) {
    ull d;
    asm("fma.rn.f32x2 %0, %1, %2, %3;" : "=l"(d) : "l"(a), "l"(b), "l"(c));
    return d;
}
__device__ __forceinline__ ull fadd2(ull a, ull b) {
    ull d;
    asm("add.rn.f32x2 %0, %1, %2;" : "=l"(d) : "l"(a), "l"(b));
    return d;
}
// 2*relu(a) packed: a + |a|
__device__ __forceinline__ ull relu2x2(ull a) {
    return fadd2(a, a & 0x7FFFFFFF7FFFFFFFULL);
}
__device__ __forceinline__ ull pack2(float lo, float hi) {
    ull d;
    asm("mov.b64 %0, {%1, %2};" : "=l"(d) : "f"(lo), "f"(hi));
    return d;
}
__device__ __forceinline__ float2 unpack2(ull v) {
    float2 r;
    asm("mov.b64 {%0, %1}, %2;" : "=f"(r.x), "=f"(r.y) : "l"(v));
    return r;
}

// Fused: dtype detection (thread 0) + out[] init to lin_b.
__global__ void init_kernel(float* __restrict__ out, const float* __restrict__ lin_b,
                            const int* __restrict__ ei) {
    int i = blockIdx.x * blockDim.x + threadIdx.x;
    if (i == 0) {
        int is64 = 1;
        for (int k = 1; k < 128; k += 2)
            if (ei[k] != 0) { is64 = 0; break; }
        g_is64 = is64;
    }
    if (i < NEDGE) out[i] = lin_b[0];
}

__global__ void __launch_bounds__(THREADS, 2) convkb_kernel(
    const float* __restrict__ h,
    const float* __restrict__ g,
    const int* __restrict__ edge_idx,    // [2,E], low int32 words read
    const int* __restrict__ edge_type,   // [E]
    const float* __restrict__ conv_w,    // [C,3]
    const float* __restrict__ conv_b,    // [C]
    const float* __restrict__ lin_w,     // [C*D]
    float* __restrict__ out)             // [E], pre-initialized to lin_b
{
    const int lane = threadIdx.x & 31;
    const int warp = threadIdx.x >> 5;

    // ---- Edge-invariant register state: warp covers channels cb..cb+7 ----
    // Lane L owns d = 4L .. 4L+3 (two packed d-pairs). Shared by both edges.
    const int cb = warp * 8;
    ull w0d[8], w1d[8], w2d[8], bd[8], lwr[8][2];
    {
        const float4* lw4 = (const float4*)lin_w;
#pragma unroll
        for (int ch = 0; ch < 8; ++ch) {
            int c = cb + ch;
            float a0 = conv_w[3 * c + 0], a1 = conv_w[3 * c + 1], a2 = conv_w[3 * c + 2];
            float bb = conv_b[c];
            w0d[ch] = pack2(a0, a0);
            w1d[ch] = pack2(a1, a1);
            w2d[ch] = pack2(a2, a2);
            bd[ch]  = pack2(bb, bb);
            float4 A = lw4[c * 32 + lane];   // lw[c, 4L .. 4L+3]
            lwr[ch][0] = pack2(0.5f * A.x, 0.5f * A.y);   // relu-trick pre-scale
            lwr[ch][1] = pack2(0.5f * A.z, 0.5f * A.w);
        }
    }

    const int stride = g_is64 ? 2 : 1;

    // ---- Pipeline prologue: data for pair(0) = (e0, e0+G); indices for pair(1) ----
    int e = (int)blockIdx.x;                       // ea=e, eb=e+G
    ulonglong2 UA, VA, RA, UB, VB, RB;
    {
        int ra = edge_idx[(size_t)stride * e];
        int ca = edge_idx[(size_t)stride * (NEDGE + e)];
        int ta = edge_type[(size_t)stride * e];
        int eb = e + G;                            // < 592 < NEDGE: safe
        int rb = edge_idx[(size_t)stride * eb];
        int cbx = edge_idx[(size_t)stride * (NEDGE + eb)];
        int tb = edge_type[(size_t)stride * eb];
        UA = ((const ulonglong2*)(h + (size_t)ra * D))[lane];
        VA = ((const ulonglong2*)(h + (size_t)ca * D))[lane];
        RA = ((const ulonglong2*)(g + (size_t)ta * D))[lane];
        UB = ((const ulonglong2*)(h + (size_t)rb * D))[lane];
        VB = ((const ulonglong2*)(h + (size_t)cbx * D))[lane];
        RB = ((const ulonglong2*)(g + (size_t)tb * D))[lane];
    }
    int ea1 = min(e + STEP, NEDGE - 1);            // clamp: safe addr, discarded
    int eb1 = min(e + STEP + G, NEDGE - 1);
    int rowA1 = edge_idx[(size_t)stride * ea1];
    int colA1 = edge_idx[(size_t)stride * (NEDGE + ea1)];
    int relA1 = edge_type[(size_t)stride * ea1];
    int rowB1 = edge_idx[(size_t)stride * eb1];
    int colB1 = edge_idx[(size_t)stride * (NEDGE + eb1)];
    int relB1 = edge_type[(size_t)stride * eb1];

    for (; e < NEDGE; e += STEP) {
        // Issue next pair's gathers (indices staged last iteration).
        ulonglong2 nUA = ((const ulonglong2*)(h + (size_t)rowA1 * D))[lane];
        ulonglong2 nVA = ((const ulonglong2*)(h + (size_t)colA1 * D))[lane];
        ulonglong2 nRA = ((const ulonglong2*)(g + (size_t)relA1 * D))[lane];
        ulonglong2 nUB = ((const ulonglong2*)(h + (size_t)rowB1 * D))[lane];
        ulonglong2 nVB = ((const ulonglong2*)(h + (size_t)colB1 * D))[lane];
        ulonglong2 nRB = ((const ulonglong2*)(g + (size_t)relB1 * D))[lane];

        // Stage indices for pair(i+2).
        int ea2 = min(e + 2 * STEP, NEDGE - 1);
        int eb2 = min(e + 2 * STEP + G, NEDGE - 1);
        int rowA2 = edge_idx[(size_t)stride * ea2];
        int colA2 = edge_idx[(size_t)stride * (NEDGE + ea2)];
        int relA2 = edge_type[(size_t)stride * ea2];
        int rowB2 = edge_idx[(size_t)stride * eb2];
        int colB2 = edge_idx[(size_t)stride * (NEDGE + eb2)];
        int relB2 = edge_type[(size_t)stride * eb2];

        // ---- Compute both edges (interleaved for ILP; shared params) ----
        ull a0A = 0ULL, a1A = 0ULL, a0B = 0ULL, a1B = 0ULL;
#pragma unroll
        for (int ch = 0; ch < 8; ++ch) {
            ull t0a = ffma2(w2d[ch], RA.x, bd[ch]);
            ull t1a = ffma2(w2d[ch], RA.y, bd[ch]);
            ull t0b = ffma2(w2d[ch], RB.x, bd[ch]);
            ull t1b = ffma2(w2d[ch], RB.y, bd[ch]);
            t0a = ffma2(w1d[ch], VA.x, t0a);
            t1a = ffma2(w1d[ch], VA.y, t1a);
            t0b = ffma2(w1d[ch], VB.x, t0b);
            t1b = ffma2(w1d[ch], VB.y, t1b);
            t0a = ffma2(w0d[ch], UA.x, t0a);
            t1a = ffma2(w0d[ch], UA.y, t1a);
            t0b = ffma2(w0d[ch], UB.x, t0b);
            t1b = ffma2(w0d[ch], UB.y, t1b);
            t0a = relu2x2(t0a);
            t1a = relu2x2(t1a);
            t0b = relu2x2(t0b);
            t1b = relu2x2(t1b);
            a0A = ffma2(t0a, lwr[ch][0], a0A);
            a1A = ffma2(t1a, lwr[ch][1], a1A);
            a0B = ffma2(t0b, lwr[ch][0], a0B);
            a1B = ffma2(t1b, lwr[ch][1], a1B);
        }
        float2 fA = unpack2(fadd2(a0A, a1A));
        float2 fB = unpack2(fadd2(a0B, a1B));
        float sA = fA.x + fA.y;
        float sB = fB.x + fB.y;
        // Two independent butterflies interleave in the pipeline.
#pragma unroll
        for (int off = 16; off > 0; off >>= 1) {
            sA += __shfl_xor_sync(0xffffffffu, sA, off);
            sB += __shfl_xor_sync(0xffffffffu, sB, off);
        }
        if (lane == 0) {
            atomicAdd(out + e, sA);
            int eb = e + G;
            if (eb < NEDGE) atomicAdd(out + eb, sB);
        }

        // ---- Rotate pipeline ----
        UA = nUA; VA = nVA; RA = nRA; UB = nUB; VB = nVB; RB = nRB;
        rowA1 = rowA2; colA1 = colA2; relA1 = relA2;
        rowB1 = rowB2; colB1 = colB2; relB1 = relB2;
    }
}

extern "C" void kernel_launch(void* const* d_in, const int* in_sizes, int n_in,
                              void* d_out, int out_size) {
    // Identify inputs by unique element counts (immune to metadata ordering).
    const float *h = 0, *g = 0, *conv_w = 0, *conv_b = 0, *lin_w = 0, *lin_b = 0;
    const int *edge_idx = 0, *edge_type = 0;
    for (int i = 0; i < n_in; ++i) {
        switch (in_sizes[i]) {
            case NEDGE * 128: h         = (const float*)d_in[i]; break;
            case 500 * 128:   g         = (const float*)d_in[i]; break;
            case 2 * NEDGE:   edge_idx  = (const int*)d_in[i];   break;
            case NEDGE:       edge_type = (const int*)d_in[i];   break;
            case 96:          conv_w    = (const float*)d_in[i]; break;
            case 32:          conv_b    = (const float*)d_in[i]; break;
            case 4096:        lin_w     = (const float*)d_in[i]; break;
            case 1:           lin_b     = (const float*)d_in[i]; break;
            default: break;
        }
    }
    float* out = (float*)d_out;

    init_kernel<<<(NEDGE + 255) / 256, 256>>>(out, lin_b, edge_idx);
    convkb_kernel<<<G, THREADS>>>(h, g, edge_idx, edge_type,
                                  conv_w, conv_b, lin_w, out);
}

// round 14
// speedup vs baseline: 2.2474x; 1.0647x over previous
#include <cuda_runtime.h>

// ConvKB: score[e] = sum_{c,d} relu(w0c*u_d + w1c*v_d + w2c*r_d + bc) * lw[c,d] + lb
// Warp = (2 edges, 8 channels, all 128 d) — 4 independent FFMA2 chains for ILP.
// Indices staged 1 iter ahead; gathers issued at top of iteration (occupancy covers
// the L2 latency: 3 blocks/SM). Reduction: 3-level butterfly + 4-lane atomicAdd.
// Packed f32x2 FMA, relu via (t+|t|) with lw pre-scaled 0.5, out pre-init to lin_b.

#define D 128
#define THREADS 128
#define G 444                 // grid: 148 SMs * 3 blocks
#define STEP (2 * G)          // edges consumed per iteration across grid
#define NEDGE 50000

typedef unsigned long long ull;

__device__ int g_is64;        // 1 if index arrays are int64, 0 if int32

__device__ __forceinline__ ull ffma2(ull a, ull b, ull c) {
    ull d;
    asm("fma.rn.f32x2 %0, %1, %2, %3;" : "=l"(d) : "l"(a), "l"(b), "l"(c));
    return d;
}
__device__ __forceinline__ ull fadd2(ull a, ull b) {
    ull d;
    asm("add.rn.f32x2 %0, %1, %2;" : "=l"(d) : "l"(a), "l"(b));
    return d;
}
// 2*relu(a) packed: a + |a|
__device__ __forceinline__ ull relu2x2(ull a) {
    return fadd2(a, a & 0x7FFFFFFF7FFFFFFFULL);
}
__device__ __forceinline__ ull pack2(float lo, float hi) {
    ull d;
    asm("mov.b64 %0, {%1, %2};" : "=l"(d) : "f"(lo), "f"(hi));
    return d;
}
__device__ __forceinline__ float2 unpack2(ull v) {
    float2 r;
    asm("mov.b64 {%0, %1}, %2;" : "=f"(r.x), "=f"(r.y) : "l"(v));
    return r;
}

// Fused: dtype detection (thread 0) + out[] init to lin_b.
__global__ void init_kernel(float* __restrict__ out, const float* __restrict__ lin_b,
                            const int* __restrict__ ei) {
    int i = blockIdx.x * blockDim.x + threadIdx.x;
    if (i == 0) {
        int is64 = 1;
        for (int k = 1; k < 128; k += 2)
            if (ei[k] != 0) { is64 = 0; break; }
        g_is64 = is64;
    }
    if (i < NEDGE) out[i] = lin_b[0];
}

__global__ void __launch_bounds__(THREADS, 3) convkb_kernel(
    const float* __restrict__ h,
    const float* __restrict__ g,
    const int* __restrict__ edge_idx,    // [2,E], low int32 words read
    const int* __restrict__ edge_type,   // [E]
    const float* __restrict__ conv_w,    // [C,3]
    const float* __restrict__ conv_b,    // [C]
    const float* __restrict__ lin_w,     // [C*D]
    float* __restrict__ out)             // [E], pre-initialized to lin_b
{
    const int lane = threadIdx.x & 31;
    const int warp = threadIdx.x >> 5;

    // ---- Edge-invariant register state: warp covers channels cb..cb+7 ----
    // Lane L owns d = 4L .. 4L+3 (two packed d-pairs). Shared by both edges.
    const int cb = warp * 8;
    ull w0d[8], w1d[8], w2d[8], bd[8], lwr[8][2];
    {
        const float4* lw4 = (const float4*)lin_w;
#pragma unroll
        for (int ch = 0; ch < 8; ++ch) {
            int c = cb + ch;
            float a0 = conv_w[3 * c + 0], a1 = conv_w[3 * c + 1], a2 = conv_w[3 * c + 2];
            float bb = conv_b[c];
            w0d[ch] = pack2(a0, a0);
            w1d[ch] = pack2(a1, a1);
            w2d[ch] = pack2(a2, a2);
            bd[ch]  = pack2(bb, bb);
            float4 A = lw4[c * 32 + lane];   // lw[c, 4L .. 4L+3]
            lwr[ch][0] = pack2(0.5f * A.x, 0.5f * A.y);   // relu-trick pre-scale
            lwr[ch][1] = pack2(0.5f * A.z, 0.5f * A.w);
        }
    }

    const int stride = g_is64 ? 2 : 1;

    // ---- Prologue: stage indices for pair(0) = (e0, e0+G) ----
    int e = (int)blockIdx.x;
    int rowA = edge_idx[(size_t)stride * e];
    int colA = edge_idx[(size_t)stride * (NEDGE + e)];
    int relA = edge_type[(size_t)stride * e];
    int eb0 = e + G;                               // < 888 < NEDGE: safe
    int rowB = edge_idx[(size_t)stride * eb0];
    int colB = edge_idx[(size_t)stride * (NEDGE + eb0)];
    int relB = edge_type[(size_t)stride * eb0];

    for (; e < NEDGE; e += STEP) {
        // ---- Gathers for current pair (indices staged last iteration) ----
        ulonglong2 RA = ((const ulonglong2*)(g + (size_t)relA * D))[lane];
        ulonglong2 RB = ((const ulonglong2*)(g + (size_t)relB * D))[lane];
        ulonglong2 VA = ((const ulonglong2*)(h + (size_t)colA * D))[lane];
        ulonglong2 VB = ((const ulonglong2*)(h + (size_t)colB * D))[lane];
        ulonglong2 UA = ((const ulonglong2*)(h + (size_t)rowA * D))[lane];
        ulonglong2 UB = ((const ulonglong2*)(h + (size_t)rowB * D))[lane];

        // ---- Stage indices for next pair (reuse regs after gathers issued) ----
        int ea2 = min(e + STEP, NEDGE - 1);        // clamp: safe addr, discarded
        int eb2 = min(e + STEP + G, NEDGE - 1);
        rowA = edge_idx[(size_t)stride * ea2];
        colA = edge_idx[(size_t)stride * (NEDGE + ea2)];
        relA = edge_type[(size_t)stride * ea2];
        rowB = edge_idx[(size_t)stride * eb2];
        colB = edge_idx[(size_t)stride * (NEDGE + eb2)];
        relB = edge_type[(size_t)stride * eb2];

        // ---- Compute both edges (4 independent FFMA2 chains; shared params) ----
        ull a0A = 0ULL, a1A = 0ULL, a0B = 0ULL, a1B = 0ULL;
#pragma unroll
        for (int ch = 0; ch < 8; ++ch) {
            ull t0a = ffma2(w2d[ch], RA.x, bd[ch]);
            ull t1a = ffma2(w2d[ch], RA.y, bd[ch]);
            ull t0b = ffma2(w2d[ch], RB.x, bd[ch]);
            ull t1b = ffma2(w2d[ch], RB.y, bd[ch]);
            t0a = ffma2(w1d[ch], VA.x, t0a);
            t1a = ffma2(w1d[ch], VA.y, t1a);
            t0b = ffma2(w1d[ch], VB.x, t0b);
            t1b = ffma2(w1d[ch], VB.y, t1b);
            t0a = ffma2(w0d[ch], UA.x, t0a);
            t1a = ffma2(w0d[ch], UA.y, t1a);
            t0b = ffma2(w0d[ch], UB.x, t0b);
            t1b = ffma2(w0d[ch], UB.y, t1b);
            t0a = relu2x2(t0a);
            t1a = relu2x2(t1a);
            t0b = relu2x2(t0b);
            t1b = relu2x2(t1b);
            a0A = ffma2(t0a, lwr[ch][0], a0A);
            a1A = ffma2(t1a, lwr[ch][1], a1A);
            a0B = ffma2(t0b, lwr[ch][0], a0B);
            a1B = ffma2(t1b, lwr[ch][1], a1B);
        }
        float2 fA = unpack2(fadd2(a0A, a1A));
        float2 fB = unpack2(fadd2(a0B, a1B));
        float sA = fA.x + fA.y;
        float sB = fB.x + fB.y;
        // 3-level butterfly: lanes 0..3 end up holding 4 disjoint partials.
#pragma unroll
        for (int off = 16; off >= 4; off >>= 1) {
            sA += __shfl_xor_sync(0xffffffffu, sA, off);
            sB += __shfl_xor_sync(0xffffffffu, sB, off);
        }
        if (lane < 4) {
            atomicAdd(out + e, sA);
            int eb = e + G;
            if (eb < NEDGE) atomicAdd(out + eb, sB);
        }
    }
}

extern "C" void kernel_launch(void* const* d_in, const int* in_sizes, int n_in,
                              void* d_out, int out_size) {
    // Identify inputs by unique element counts (immune to metadata ordering).
    const float *h = 0, *g = 0, *conv_w = 0, *conv_b = 0, *lin_w = 0, *lin_b = 0;
    const int *edge_idx = 0, *edge_type = 0;
    for (int i = 0; i < n_in; ++i) {
        switch (in_sizes[i]) {
            case NEDGE * 128: h         = (const float*)d_in[i]; break;
            case 500 * 128:   g         = (const float*)d_in[i]; break;
            case 2 * NEDGE:   edge_idx  = (const int*)d_in[i];   break;
            case NEDGE:       edge_type = (const int*)d_in[i];   break;
            case 96:          conv_w    = (const float*)d_in[i]; break;
            case 32:          conv_b    = (const float*)d_in[i]; break;
            case 4096:        lin_w     = (const float*)d_in[i]; break;
            case 1:           lin_b     = (const float*)d_in[i]; break;
            default: break;
        }
    }
    float* out = (float*)d_out;

    init_kernel<<<(NEDGE + 255) / 256, 256>>>(out, lin_b, edge_idx);
    convkb_kernel<<<G, THREADS>>>(h, g, edge_idx, edge_type,
                                  conv_w, conv_b, lin_w, out);
}